// round 9
// baseline (speedup 1.0000x reference)
#include <cuda_runtime.h>
#include <cstdint>

#define NN   8192
#define NE   8192
#define DEG  32
#define NNZC (NE * DEG)
#define D    32

#define CH4     2048               // one row = 2048 float4 = 32 KB
#define NCHUNK  8192
#define SKIPBIT 0x80000000u
#define EPMASK  0x7FFFFFFFu

// ---- device scratch (no allocations allowed) ----
__device__ float  g_c;
__device__ float2 g_p[NN];
__device__ float2 g_y[NN];
__device__ float  g_a[NN];
__device__ float  g_b[NE];
__device__ unsigned g_cnt[NN];        // per-row nnz count (with duplicates)
__device__ int      g_rowptr[NN + 1]; // CSR row pointers
__device__ unsigned g_wplace[NN];     // placement cursors
__device__ int      g_col[NNZC];      // CSR cols (edges per row)
__device__ unsigned g_ticket;
__device__ unsigned g_exit;
__device__ unsigned g_epoch;
__device__ unsigned g_chain_count;
__device__ unsigned g_chain_flag;     // epoch-coded: a,b,c,CSR ready
__device__ unsigned g_cflag[NCHUNK];  // epoch-coded (+SKIPBIT = value-filled)
__device__ unsigned g_bar_count;
__device__ unsigned g_bar_gen;

__device__ __forceinline__ void chain_barrier(unsigned expected) {
    __syncthreads();
    if (threadIdx.x == 0) {
        volatile unsigned* genp = (volatile unsigned*)&g_bar_gen;
        const unsigned g = *genp;
        __threadfence();
        if (atomicAdd(&g_bar_count, 1u) == expected - 1u) {
            g_bar_count = 0u;
            __threadfence();
            atomicAdd(&g_bar_gen, 1u);
        } else {
            while (*genp == g) __nanosleep(64);
            __threadfence();
        }
    }
    __syncthreads();
}

__device__ __forceinline__ void edge_reduce(const int* __restrict__ nidx, int e,
                                            const float2* __restrict__ src,
                                            int lane, unsigned lt,
                                            int& n, bool& keep, float& s0, float& s1) {
    n = nidx[e * DEG + lane];
    const unsigned peers = __match_any_sync(0xffffffffu, n);
    keep = (peers & lt) == 0u;
    s0 = 0.f; s1 = 0.f;
    if (keep) { const float2 pv = src[n]; s0 = pv.x; s1 = pv.y; }
    #pragma unroll
    for (int o = 16; o > 0; o >>= 1) {
        s0 += __shfl_xor_sync(0xffffffffu, s0, o);
        s1 += __shfl_xor_sync(0xffffffffu, s1, o);
    }
}

__global__ void __launch_bounds__(256, 4)
k_all(const float* __restrict__ x0,
      const float* __restrict__ Wl1, const float* __restrict__ Wl2,
      const float* __restrict__ Wm1, const float* __restrict__ bm1,
      const float* __restrict__ Wm2, const float* __restrict__ bm2,
      const float* __restrict__ Wm3, const float* __restrict__ bm3,
      const int* __restrict__ nidx, float* __restrict__ out, int CB) {
    const int t    = threadIdx.x;
    const int bid  = blockIdx.x;
    const int lane = t & 31;
    const unsigned ep1  = *(volatile unsigned*)&g_epoch + 1u;
    const unsigned ep1m = ep1 & EPMASK;

    if (bid < CB) {
        // ---------- fold affine chain into M (32x2) + c ------------------------
        __shared__ float q[D], u[D], v[D], w2u[D], M0[D], M1[D];
        if (t < D) {
            float s = 0.f;
            #pragma unroll
            for (int j = 0; j < D; ++j) s += Wm2[t * D + j] * Wm3[j];
            q[t] = s;
        }
        __syncthreads();
        if (t < D) {
            float su = 0.f, sv = 0.f;
            #pragma unroll
            for (int j = 0; j < D; ++j) {
                su += Wm1[t * D + j] * q[j];
                sv += Wm1[(D + t) * D + j] * q[j];
            }
            u[t] = su; v[t] = sv;
        }
        __syncthreads();
        if (t < D) {
            float s = 0.f;
            #pragma unroll
            for (int j = 0; j < D; ++j) s += Wl2[t * D + j] * u[j];
            w2u[t] = s;
        }
        if (bid == 0 && t == 0) {
            float c = bm3[0];
            #pragma unroll
            for (int j = 0; j < D; ++j) c += bm1[j] * q[j] + bm2[j] * Wm3[j];
            g_c = c;
        }
        __syncthreads();
        if (t < D) {
            float s0 = 0.f, s1 = 0.f;
            #pragma unroll
            for (int j = 0; j < D; ++j) {
                s0 += Wl1[t * D + j] * w2u[j];
                s1 += Wl1[t * D + j] * v[j];
            }
            M0[t] = s0; M1[t] = s1;
        }
        __syncthreads();

        // ---------- p[n] = x0[n] @ M ; zero y, a, cnt ---------------------------
        for (int n = bid * 256 + t; n < NN; n += CB * 256) {
            const float4* row = (const float4*)(x0 + (size_t)n * D);
            float p0 = 0.f, p1 = 0.f;
            #pragma unroll
            for (int j = 0; j < 8; ++j) {
                const float4 xv = row[j];
                p0 += xv.x * M0[4*j] + xv.y * M0[4*j+1] + xv.z * M0[4*j+2] + xv.w * M0[4*j+3];
                p1 += xv.x * M1[4*j] + xv.y * M1[4*j+1] + xv.z * M1[4*j+2] + xv.w * M1[4*j+3];
            }
            g_p[n] = make_float2(p0, p1);
            g_y[n] = make_float2(0.f, 0.f);
            g_a[n] = 0.f;
            g_cnt[n] = 0u;
        }
        chain_barrier((unsigned)CB);

        // ---------- zy: z[e] = Σ p[n∈e] ; y[n] += z[e] ; count CSR --------------
        const unsigned lt = (1u << lane) - 1u;
        const int CW = CB * 8;
        for (int e = bid * 8 + (t >> 5); e < NE; e += CW) {
            int n; bool keep; float s0, s1;
            edge_reduce(nidx, e, g_p, lane, lt, n, keep, s0, s1);
            atomicAdd(&g_cnt[n], 1u);          // duplicates included (benign)
            if (keep) {
                atomicAdd(&g_y[n].x, s0);
                atomicAdd(&g_y[n].y, s1);
            }
        }
        chain_barrier((unsigned)CB);

        // ---------- exclusive scan of cnt -> rowptr, wplace (block 0) -----------
        if (bid == 0) {
            __shared__ unsigned s_sum[256];
            unsigned s = 0u;
            const int base = t * (NN / 256);   // 32 elems per thread
            #pragma unroll
            for (int k = 0; k < NN / 256; ++k) s += g_cnt[base + k];
            s_sum[t] = s;
            __syncthreads();
            // Hillis-Steele inclusive scan over 256
            #pragma unroll
            for (int o = 1; o < 256; o <<= 1) {
                unsigned v = (t >= o) ? s_sum[t - o] : 0u;
                __syncthreads();
                s_sum[t] += v;
                __syncthreads();
            }
            unsigned off = (t == 0) ? 0u : s_sum[t - 1];
            #pragma unroll
            for (int k = 0; k < NN / 256; ++k) {
                const unsigned c = g_cnt[base + k];
                g_rowptr[base + k] = (int)off;
                g_wplace[base + k] = off;
                off += c;
            }
            if (t == 255) g_rowptr[NN] = (int)off;   // == NNZC
        }
        chain_barrier((unsigned)CB);

        // ---------- ta: t[e] = Σ y[n∈e] ; b,a ; place CSR cols ------------------
        for (int e = bid * 8 + (t >> 5); e < NE; e += CW) {
            int n; bool keep; float s0, s1;
            edge_reduce(nidx, e, g_y, lane, lt, n, keep, s0, s1);
            const unsigned pos = atomicAdd(&g_wplace[n], 1u);
            g_col[pos] = e;
            if (lane == 0) g_b[e] = s1;
            if (keep) atomicAdd(&g_a[n], s0);
        }
        __threadfence();
        __syncthreads();
        if (t == 0) {
            if (atomicAdd(&g_chain_count, 1u) == (unsigned)CB - 1u) {
                g_chain_count = 0u;
                atomicExch(&g_chain_flag, ep1);
            }
        }
    }

    // ---------- fill: zeros always; patch values in-row once chain is done ------
    {
        const float4 z4 = make_float4(0.f, 0.f, 0.f, 0.f);
        float4* out4 = (float4*)out;
        __shared__ unsigned s_t[2];
        __shared__ int s_ch[2];
        if (t == 0) {
            s_t[0]  = atomicAdd(&g_ticket, 1u);
            s_ch[0] = (*(volatile unsigned*)&g_chain_flag == ep1);
        }
        __syncthreads();
        int par = 0;
        for (;;) {
            const unsigned cur = s_t[par];
            const int chained  = s_ch[par];
            if (cur >= (unsigned)NCHUNK) break;
            if (t == 0) {
                s_t[par ^ 1]  = atomicAdd(&g_ticket, 1u);
                s_ch[par ^ 1] = (*(volatile unsigned*)&g_chain_flag == ep1);
            }
            float4* dst = out4 + (size_t)cur * CH4;
            // pure zero store loop (hot path — keep untouched)
            #pragma unroll
            for (int j = 0; j < CH4 / 256; ++j)
                __stcs(&dst[t + j * 256], z4);
            if (chained) {
                __syncthreads();                   // zeros ordered before patches
                // patch this row's nnz in place (lines still L2-resident)
                const float ac = g_a[cur] + g_c;
                const int start = g_rowptr[cur];
                const int end   = g_rowptr[cur + 1];
                float* dstf = (float*)dst;
                for (int k = start + t; k < end; k += 256) {
                    const int e = g_col[k];
                    dstf[e] = ac + g_b[e];
                }
                __syncthreads();                   // ticket buffer reusable
                if (t == 0) atomicExch(&g_cflag[cur], ep1 | SKIPBIT);
            } else {
                __threadfence();                   // zeros visible before flag
                __syncthreads();
                if (t == 0) atomicExch(&g_cflag[cur], ep1);
            }
            par ^= 1;
        }
    }

    // ---------- scatter: only rows zero-filled before chain completion ----------
    {
        if (t == 0) {
            volatile unsigned* cf = (volatile unsigned*)&g_chain_flag;
            while (*cf != ep1) __nanosleep(64);
        }
        __syncthreads();
        __threadfence();
        const float cc = g_c;
        for (int i = bid * 256 + t; i < NNZC; i += gridDim.x * 256) {
            const int n = __ldg(&nidx[i]);
            const int e = i >> 5;                  // edge_idx = repeat(arange(E), DEG)
            volatile unsigned* rf = (volatile unsigned*)&g_cflag[n];
            unsigned f;
            while (((f = *rf) & EPMASK) != ep1m) __nanosleep(32);
            if (f & SKIPBIT) continue;             // row already value-patched
            __threadfence();
            out[(size_t)n * NE + e] = g_a[n] + g_b[e] + cc;
        }
    }

    // ---------- exit: last block resets queue state and bumps epoch -------------
    __syncthreads();
    if (t == 0) {
        __threadfence();
        if (atomicAdd(&g_exit, 1u) == gridDim.x - 1u) {
            g_exit   = 0u;
            g_ticket = 0u;
            atomicExch(&g_epoch, ep1);
        }
    }
}

extern "C" void kernel_launch(void* const* d_in, const int* in_sizes, int n_in,
                              void* d_out, int out_size) {
    const float* x0   = (const float*)d_in[0];
    const float* Wl1  = (const float*)d_in[2];
    const float* Wl2  = (const float*)d_in[3];
    const float* Wm1  = (const float*)d_in[4];
    const float* bm1  = (const float*)d_in[5];
    const float* Wm2  = (const float*)d_in[6];
    const float* bm2  = (const float*)d_in[7];
    const float* Wm3  = (const float*)d_in[8];
    const float* bm3  = (const float*)d_in[9];
    const int*   nidx = (const int*)d_in[10];

    int dev = 0;
    cudaGetDevice(&dev);
    int sms = 0;
    cudaDeviceGetAttribute(&sms, cudaDevAttrMultiProcessorCount, dev);
    int nb = 0;
    cudaOccupancyMaxActiveBlocksPerMultiprocessor(&nb, k_all, 256, 0);
    if (sms <= 0) sms = 148;
    if (nb  <= 0) nb  = 4;
    if (nb  >  4) nb  = 4;
    int grid = sms * nb;
    int cb = grid / 2 < 128 ? grid / 2 : 128;

    k_all<<<grid, 256>>>(x0, Wl1, Wl2, Wm1, bm1, Wm2, bm2, Wm3, bm3,
                         nidx, (float*)d_out, cb);
}

// round 10
// speedup vs baseline: 1.2024x; 1.2024x over previous
#include <cuda_runtime.h>
#include <cstdint>

#define NN   8192
#define NE   8192
#define DEG  32
#define NNZC (NE * DEG)
#define D    32

// Fill chunk = FOUR output rows: 8192 float4 = 128 KB (R4/R6-proven grain)
#define ROWS_PER_CHUNK 4
#define CH4    (ROWS_PER_CHUNK * NE / 4)     // 8192 float4
#define NCHUNK (NN / ROWS_PER_CHUNK)         // 2048

// ---- device scratch (no allocations allowed) ----
__device__ float  g_c;
__device__ float2 g_p[NN];          // p[n] = x_0[n] @ M
__device__ float2 g_y[NN];          // y[n] = sum_{e∋n} z[e]
__device__ float  g_a[NN];          // a[n] = sum_{e∋n} t[e].0
__device__ float  g_b[NE];          // b[e] = t[e].1
__device__ unsigned g_ticket;       // fill chunk queue
__device__ unsigned g_exit;         // exit counter (last block resets state)
__device__ unsigned g_epoch;        // launch epoch (monotonic across replays)
__device__ unsigned g_chain_count;  // chain completion counter
__device__ unsigned g_chain_flag;   // epoch-coded: a,b,c ready
__device__ unsigned g_cflag[NCHUNK];// epoch-coded: chunk (4 rows) filled
__device__ unsigned g_bar_count;    // chain-internal barrier
__device__ unsigned g_bar_gen;

// Sense-free generation barrier among the CB chain blocks.
__device__ __forceinline__ void chain_barrier(unsigned expected) {
    __syncthreads();
    if (threadIdx.x == 0) {
        volatile unsigned* genp = (volatile unsigned*)&g_bar_gen;
        const unsigned g = *genp;
        __threadfence();
        if (atomicAdd(&g_bar_count, 1u) == expected - 1u) {
            g_bar_count = 0u;
            __threadfence();
            atomicAdd(&g_bar_gen, 1u);
        } else {
            while (*genp == g) __nanosleep(64);
            __threadfence();
        }
    }
    __syncthreads();
}

// Warp-level: dedup-gather-sum of src over one edge.
__device__ __forceinline__ void edge_reduce(const int* __restrict__ nidx, int e,
                                            const float2* __restrict__ src,
                                            int lane, unsigned lt,
                                            int& n, bool& keep, float& s0, float& s1) {
    n = nidx[e * DEG + lane];
    const unsigned peers = __match_any_sync(0xffffffffu, n);
    keep = (peers & lt) == 0u;
    s0 = 0.f; s1 = 0.f;
    if (keep) { const float2 pv = src[n]; s0 = pv.x; s1 = pv.y; }
    #pragma unroll
    for (int o = 16; o > 0; o >>= 1) {
        s0 += __shfl_xor_sync(0xffffffffu, s0, o);
        s1 += __shfl_xor_sync(0xffffffffu, s1, o);
    }
}

__global__ void __launch_bounds__(256, 4)
k_all(const float* __restrict__ x0,
      const float* __restrict__ Wl1, const float* __restrict__ Wl2,
      const float* __restrict__ Wm1, const float* __restrict__ bm1,
      const float* __restrict__ Wm2, const float* __restrict__ bm2,
      const float* __restrict__ Wm3, const float* __restrict__ bm3,
      const int* __restrict__ nidx, float* __restrict__ out, int CB) {
    const int t    = threadIdx.x;
    const int bid  = blockIdx.x;
    const int lane = t & 31;
    const unsigned ep1 = *(volatile unsigned*)&g_epoch + 1u;   // this launch's tag

    if (bid < CB) {
        // ---------- fold affine chain into M (32x2) + c (redundant per block) ----
        __shared__ float q[D], u[D], v[D], w2u[D], M0[D], M1[D];
        if (t < D) {
            float s = 0.f;
            #pragma unroll
            for (int j = 0; j < D; ++j) s += Wm2[t * D + j] * Wm3[j];
            q[t] = s;
        }
        __syncthreads();
        if (t < D) {
            float su = 0.f, sv = 0.f;
            #pragma unroll
            for (int j = 0; j < D; ++j) {
                su += Wm1[t * D + j] * q[j];
                sv += Wm1[(D + t) * D + j] * q[j];
            }
            u[t] = su; v[t] = sv;
        }
        __syncthreads();
        if (t < D) {
            float s = 0.f;
            #pragma unroll
            for (int j = 0; j < D; ++j) s += Wl2[t * D + j] * u[j];
            w2u[t] = s;
        }
        if (bid == 0 && t == 0) {
            float c = bm3[0];
            #pragma unroll
            for (int j = 0; j < D; ++j) c += bm1[j] * q[j] + bm2[j] * Wm3[j];
            g_c = c;
        }
        __syncthreads();
        if (t < D) {
            float s0 = 0.f, s1 = 0.f;
            #pragma unroll
            for (int j = 0; j < D; ++j) {
                s0 += Wl1[t * D + j] * w2u[j];
                s1 += Wl1[t * D + j] * v[j];
            }
            M0[t] = s0; M1[t] = s1;
        }
        __syncthreads();

        // ---------- p[n] = x0[n] @ M ; zero y, a -------------------------------
        for (int n = bid * 256 + t; n < NN; n += CB * 256) {
            const float4* row = (const float4*)(x0 + (size_t)n * D);
            float p0 = 0.f, p1 = 0.f;
            #pragma unroll
            for (int j = 0; j < 8; ++j) {
                const float4 xv = row[j];
                p0 += xv.x * M0[4*j] + xv.y * M0[4*j+1] + xv.z * M0[4*j+2] + xv.w * M0[4*j+3];
                p1 += xv.x * M1[4*j] + xv.y * M1[4*j+1] + xv.z * M1[4*j+2] + xv.w * M1[4*j+3];
            }
            g_p[n] = make_float2(p0, p1);
            g_y[n] = make_float2(0.f, 0.f);
            g_a[n] = 0.f;
        }
        chain_barrier((unsigned)CB);

        // ---------- zy: z[e] = Σ p[n∈e] ; y[n] += z[e] -------------------------
        const unsigned lt = (1u << lane) - 1u;
        const int CW = CB * 8;
        for (int e = bid * 8 + (t >> 5); e < NE; e += CW) {
            int n; bool keep; float s0, s1;
            edge_reduce(nidx, e, g_p, lane, lt, n, keep, s0, s1);
            if (keep) {
                atomicAdd(&g_y[n].x, s0);
                atomicAdd(&g_y[n].y, s1);
            }
        }
        chain_barrier((unsigned)CB);

        // ---------- ta: t[e] = Σ y[n∈e] ; b[e] = t.1 ; a[n] += t.0 -------------
        for (int e = bid * 8 + (t >> 5); e < NE; e += CW) {
            int n; bool keep; float s0, s1;
            edge_reduce(nidx, e, g_y, lane, lt, n, keep, s0, s1);
            if (lane == 0) g_b[e] = s1;
            if (keep) atomicAdd(&g_a[n], s0);
        }
        // publish a, b, c
        __threadfence();
        __syncthreads();
        if (t == 0) {
            if (atomicAdd(&g_chain_count, 1u) == (unsigned)CB - 1u) {
                g_chain_count = 0u;
                atomicExch(&g_chain_flag, ep1);
            }
        }
        // fall through: chain blocks join the fill
    }

    // ---------- zero-fill: per-block ticket queue, 4 rows (128 KB) per grab -----
    {
        const float4 z4 = make_float4(0.f, 0.f, 0.f, 0.f);
        float4* out4 = (float4*)out;
        __shared__ unsigned s_t[2];
        if (t == 0) s_t[0] = atomicAdd(&g_ticket, 1u);
        __syncthreads();
        int par = 0;
        for (;;) {
            const unsigned cur = s_t[par];            // uniform chunk index
            if (cur >= (unsigned)NCHUNK) break;
            if (t == 0) s_t[par ^ 1] = atomicAdd(&g_ticket, 1u);
            float4* dst = out4 + (size_t)cur * CH4;
            #pragma unroll 8
            for (int i = t; i < CH4; i += 256)
                __stcs(&dst[i], z4);
            __threadfence();                          // stores visible before flag
            __syncthreads();                          // all threads fenced; ticket ready
            if (t == 0) atomicExch(&g_cflag[cur], ep1);
            par ^= 1;
        }
    }

    // ---------- scatter: per-chunk dependency, no global barrier ----------------
    {
        if (t == 0) {
            volatile unsigned* cf = (volatile unsigned*)&g_chain_flag;
            while (*cf != ep1) __nanosleep(64);
        }
        __syncthreads();
        __threadfence();
        const float cc = g_c;
        for (int i = bid * 256 + t; i < NNZC; i += gridDim.x * 256) {
            const int n = __ldg(&nidx[i]);
            const int e = i >> 5;      // edge_idx = repeat(arange(E), DEG)
            volatile unsigned* rf = (volatile unsigned*)&g_cflag[n / ROWS_PER_CHUNK];
            while (*rf != ep1) __nanosleep(32);        // chunk's zeros committed?
            __threadfence();
            out[(size_t)n * NE + e] = g_a[n] + g_b[e] + cc;
        }
    }

    // ---------- exit: last block resets queue state and bumps epoch -------------
    __syncthreads();
    if (t == 0) {
        __threadfence();
        if (atomicAdd(&g_exit, 1u) == gridDim.x - 1u) {
            g_exit   = 0u;
            g_ticket = 0u;           // safe: every block has left the fill loop
            atomicExch(&g_epoch, ep1);
        }
    }
}

extern "C" void kernel_launch(void* const* d_in, const int* in_sizes, int n_in,
                              void* d_out, int out_size) {
    const float* x0   = (const float*)d_in[0];
    // d_in[1] = dense incidence (unused)
    const float* Wl1  = (const float*)d_in[2];
    const float* Wl2  = (const float*)d_in[3];
    const float* Wm1  = (const float*)d_in[4];
    const float* bm1  = (const float*)d_in[5];
    const float* Wm2  = (const float*)d_in[6];
    const float* bm2  = (const float*)d_in[7];
    const float* Wm3  = (const float*)d_in[8];
    const float* bm3  = (const float*)d_in[9];
    const int*   nidx = (const int*)d_in[10];
    // d_in[11] = edge_idx (implied: e = i >> 5)

    int dev = 0;
    cudaGetDevice(&dev);
    int sms = 0;
    cudaDeviceGetAttribute(&sms, cudaDevAttrMultiProcessorCount, dev);
    int nb = 0;
    cudaOccupancyMaxActiveBlocksPerMultiprocessor(&nb, k_all, 256, 0);
    if (sms <= 0) sms = 148;
    if (nb  <= 0) nb  = 4;
    if (nb  >  4) nb  = 4;     // R4/R6-proven stream layout
    int grid = sms * nb;
    int cb = grid / 2 < 128 ? grid / 2 : 128;

    k_all<<<grid, 256>>>(x0, Wl1, Wl2, Wm1, bm1, Wm2, bm2, Wm3, bm3,
                         nidx, (float*)d_out, cb);
}

// round 11
// speedup vs baseline: 1.2304x; 1.0233x over previous
#include <cuda_runtime.h>
#include <cstdint>

#define NN   8192
#define NE   8192
#define DEG  32
#define NNZC (NE * DEG)
#define D    32

// Fill ticket = EIGHT rows (256 KB); each warp fills ONE row (32 KB contiguous).
#define ROWS_PER_CHUNK 8
#define ROW4   (NE / 4)                      // 2048 float4 per row
#define NCHUNK (NN / ROWS_PER_CHUNK)         // 1024

// ---- device scratch (no allocations allowed) ----
__device__ float  g_c;
__device__ float2 g_p[NN];          // p[n] = x_0[n] @ M
__device__ float2 g_y[NN];          // y[n] = sum_{e∋n} z[e]
__device__ float  g_a[NN];          // a[n] = sum_{e∋n} t[e].0
__device__ float  g_b[NE];          // b[e] = t[e].1
__device__ unsigned g_ticket;       // fill chunk queue
__device__ unsigned g_exit;         // exit counter (last block resets state)
__device__ unsigned g_epoch;        // launch epoch (monotonic across replays)
__device__ unsigned g_chain_count;  // chain completion counter
__device__ unsigned g_chain_flag;   // epoch-coded: a,b,c ready
__device__ unsigned g_rflag[NN];    // epoch-coded: row filled
__device__ unsigned g_bar_count;    // chain-internal barrier
__device__ unsigned g_bar_gen;

// Sense-free generation barrier among the CB chain blocks.
__device__ __forceinline__ void chain_barrier(unsigned expected) {
    __syncthreads();
    if (threadIdx.x == 0) {
        volatile unsigned* genp = (volatile unsigned*)&g_bar_gen;
        const unsigned g = *genp;
        __threadfence();
        if (atomicAdd(&g_bar_count, 1u) == expected - 1u) {
            g_bar_count = 0u;
            __threadfence();
            atomicAdd(&g_bar_gen, 1u);
        } else {
            while (*genp == g) __nanosleep(64);
            __threadfence();
        }
    }
    __syncthreads();
}

// Warp-level: dedup-gather-sum of src over one edge.
__device__ __forceinline__ void edge_reduce(const int* __restrict__ nidx, int e,
                                            const float2* __restrict__ src,
                                            int lane, unsigned lt,
                                            int& n, bool& keep, float& s0, float& s1) {
    n = nidx[e * DEG + lane];
    const unsigned peers = __match_any_sync(0xffffffffu, n);
    keep = (peers & lt) == 0u;
    s0 = 0.f; s1 = 0.f;
    if (keep) { const float2 pv = src[n]; s0 = pv.x; s1 = pv.y; }
    #pragma unroll
    for (int o = 16; o > 0; o >>= 1) {
        s0 += __shfl_xor_sync(0xffffffffu, s0, o);
        s1 += __shfl_xor_sync(0xffffffffu, s1, o);
    }
}

__global__ void __launch_bounds__(256, 4)
k_all(const float* __restrict__ x0,
      const float* __restrict__ Wl1, const float* __restrict__ Wl2,
      const float* __restrict__ Wm1, const float* __restrict__ bm1,
      const float* __restrict__ Wm2, const float* __restrict__ bm2,
      const float* __restrict__ Wm3, const float* __restrict__ bm3,
      const int* __restrict__ nidx, float* __restrict__ out, int CB) {
    const int t    = threadIdx.x;
    const int bid  = blockIdx.x;
    const int lane = t & 31;
    const int wid  = t >> 5;
    const unsigned ep1 = *(volatile unsigned*)&g_epoch + 1u;   // this launch's tag

    if (bid < CB) {
        // ---------- fold affine chain into M (32x2) + c (redundant per block) ----
        __shared__ float q[D], u[D], v[D], w2u[D], M0[D], M1[D];
        if (t < D) {
            float s = 0.f;
            #pragma unroll
            for (int j = 0; j < D; ++j) s += Wm2[t * D + j] * Wm3[j];
            q[t] = s;
        }
        __syncthreads();
        if (t < D) {
            float su = 0.f, sv = 0.f;
            #pragma unroll
            for (int j = 0; j < D; ++j) {
                su += Wm1[t * D + j] * q[j];
                sv += Wm1[(D + t) * D + j] * q[j];
            }
            u[t] = su; v[t] = sv;
        }
        __syncthreads();
        if (t < D) {
            float s = 0.f;
            #pragma unroll
            for (int j = 0; j < D; ++j) s += Wl2[t * D + j] * u[j];
            w2u[t] = s;
        }
        if (bid == 0 && t == 0) {
            float c = bm3[0];
            #pragma unroll
            for (int j = 0; j < D; ++j) c += bm1[j] * q[j] + bm2[j] * Wm3[j];
            g_c = c;
        }
        __syncthreads();
        if (t < D) {
            float s0 = 0.f, s1 = 0.f;
            #pragma unroll
            for (int j = 0; j < D; ++j) {
                s0 += Wl1[t * D + j] * w2u[j];
                s1 += Wl1[t * D + j] * v[j];
            }
            M0[t] = s0; M1[t] = s1;
        }
        __syncthreads();

        // ---------- p[n] = x0[n] @ M ; zero y, a -------------------------------
        for (int n = bid * 256 + t; n < NN; n += CB * 256) {
            const float4* row = (const float4*)(x0 + (size_t)n * D);
            float p0 = 0.f, p1 = 0.f;
            #pragma unroll
            for (int j = 0; j < 8; ++j) {
                const float4 xv = row[j];
                p0 += xv.x * M0[4*j] + xv.y * M0[4*j+1] + xv.z * M0[4*j+2] + xv.w * M0[4*j+3];
                p1 += xv.x * M1[4*j] + xv.y * M1[4*j+1] + xv.z * M1[4*j+2] + xv.w * M1[4*j+3];
            }
            g_p[n] = make_float2(p0, p1);
            g_y[n] = make_float2(0.f, 0.f);
            g_a[n] = 0.f;
        }
        chain_barrier((unsigned)CB);

        // ---------- zy: z[e] = Σ p[n∈e] ; y[n] += z[e] -------------------------
        const unsigned lt = (1u << lane) - 1u;
        const int CW = CB * 8;
        for (int e = bid * 8 + wid; e < NE; e += CW) {
            int n; bool keep; float s0, s1;
            edge_reduce(nidx, e, g_p, lane, lt, n, keep, s0, s1);
            if (keep) {
                atomicAdd(&g_y[n].x, s0);
                atomicAdd(&g_y[n].y, s1);
            }
        }
        chain_barrier((unsigned)CB);

        // ---------- ta: t[e] = Σ y[n∈e] ; b[e] = t.1 ; a[n] += t.0 -------------
        for (int e = bid * 8 + wid; e < NE; e += CW) {
            int n; bool keep; float s0, s1;
            edge_reduce(nidx, e, g_y, lane, lt, n, keep, s0, s1);
            if (lane == 0) g_b[e] = s1;
            if (keep) atomicAdd(&g_a[n], s0);
        }
        // publish a, b, c
        __threadfence();
        __syncthreads();
        if (t == 0) {
            if (atomicAdd(&g_chain_count, 1u) == (unsigned)CB - 1u) {
                g_chain_count = 0u;
                atomicExch(&g_chain_flag, ep1);
            }
        }
        // fall through: chain blocks join the fill
    }

    // ---------- zero-fill: block tickets of 8 rows; warp-per-row, per-row flags -
    {
        const float4 z4 = make_float4(0.f, 0.f, 0.f, 0.f);
        float4* out4 = (float4*)out;
        __shared__ unsigned s_t[2];
        if (t == 0) s_t[0] = atomicAdd(&g_ticket, 1u);
        __syncthreads();
        int par = 0;
        for (;;) {
            const unsigned cur = s_t[par];            // uniform chunk index
            if (cur >= (unsigned)NCHUNK) break;
            if (t == 0) s_t[par ^ 1] = atomicAdd(&g_ticket, 1u);
            const unsigned row = cur * ROWS_PER_CHUNK + wid;   // this warp's row
            float4* dst = out4 + (size_t)row * ROW4 + lane;
            #pragma unroll 8
            for (int j = 0; j < ROW4 / 32; ++j)       // 64 x STG.128 per lane
                __stcs(&dst[(size_t)j * 32], z4);
            __threadfence();                          // this lane's stores visible
            __syncwarp();                             // all lanes fenced
            if (lane == 0) atomicExch(&g_rflag[row], ep1);
            __syncthreads();                          // ticket buffer ready/reusable
            par ^= 1;
        }
    }

    // ---------- scatter: per-row dependency, no global barrier ------------------
    {
        if (t == 0) {
            volatile unsigned* cf = (volatile unsigned*)&g_chain_flag;
            while (*cf != ep1) __nanosleep(64);
        }
        __syncthreads();
        __threadfence();
        const float cc = g_c;
        for (int i = bid * 256 + t; i < NNZC; i += gridDim.x * 256) {
            const int n = __ldg(&nidx[i]);
            const int e = i >> 5;      // edge_idx = repeat(arange(E), DEG)
            volatile unsigned* rf = (volatile unsigned*)&g_rflag[n];
            while (*rf != ep1) __nanosleep(32);        // row zeros committed?
            __threadfence();
            out[(size_t)n * NE + e] = g_a[n] + g_b[e] + cc;
        }
    }

    // ---------- exit: last block resets queue state and bumps epoch -------------
    __syncthreads();
    if (t == 0) {
        __threadfence();
        if (atomicAdd(&g_exit, 1u) == gridDim.x - 1u) {
            g_exit   = 0u;
            g_ticket = 0u;           // safe: every block has left the fill loop
            atomicExch(&g_epoch, ep1);
        }
    }
}

extern "C" void kernel_launch(void* const* d_in, const int* in_sizes, int n_in,
                              void* d_out, int out_size) {
    const float* x0   = (const float*)d_in[0];
    // d_in[1] = dense incidence (unused)
    const float* Wl1  = (const float*)d_in[2];
    const float* Wl2  = (const float*)d_in[3];
    const float* Wm1  = (const float*)d_in[4];
    const float* bm1  = (const float*)d_in[5];
    const float* Wm2  = (const float*)d_in[6];
    const float* bm2  = (const float*)d_in[7];
    const float* Wm3  = (const float*)d_in[8];
    const float* bm3  = (const float*)d_in[9];
    const int*   nidx = (const int*)d_in[10];
    // d_in[11] = edge_idx (implied: e = i >> 5)

    int dev = 0;
    cudaGetDevice(&dev);
    int sms = 0;
    cudaDeviceGetAttribute(&sms, cudaDevAttrMultiProcessorCount, dev);
    int nb = 0;
    cudaOccupancyMaxActiveBlocksPerMultiprocessor(&nb, k_all, 256, 0);
    if (sms <= 0) sms = 148;
    if (nb  <= 0) nb  = 4;
    if (nb  >  4) nb  = 4;     // R4/R6-proven stream layout
    int grid = sms * nb;
    int cb = grid / 2 < 128 ? grid / 2 : 128;

    k_all<<<grid, 256>>>(x0, Wl1, Wl2, Wm1, bm1, Wm2, bm2, Wm3, bm3,
                         nidx, (float*)d_out, cb);
}

// round 12
// speedup vs baseline: 1.3501x; 1.0973x over previous
#include <cuda_runtime.h>
#include <cstdint>

#define NN   8192
#define NE   8192
#define DEG  32
#define NNZC (NE * DEG)
#define D    32

// Fill chunk = ONE output row: 2048 float4 = 8192 floats = 32 KB
#define CH4    2048
#define NCHUNK 8192

// ---- device scratch (no allocations allowed) ----
__device__ float  g_c;
__device__ float2 g_p[NN];          // p[n] = x_0[n] @ M
__device__ float2 g_y[NN];          // y[n] = sum_{e∋n} z[e]
__device__ float  g_a[NN];          // a[n] = sum_{e∋n} t[e].0
__device__ float  g_b[NE];          // b[e] = t[e].1
__device__ unsigned g_ticket;       // fill row queue
__device__ unsigned g_exit;         // exit counter (last block resets state)
__device__ unsigned g_epoch;        // launch epoch (monotonic across replays)
__device__ unsigned g_chain_count;  // chain completion counter
__device__ unsigned g_chain_flag;   // epoch-coded: a,b,c ready
__device__ unsigned g_cflag[NCHUNK];// epoch-coded: row filled
__device__ unsigned g_bar_count;    // chain-internal barrier
__device__ unsigned g_bar_gen;

// Sense-free generation barrier among the CB chain blocks.
__device__ __forceinline__ void chain_barrier(unsigned expected) {
    __syncthreads();
    if (threadIdx.x == 0) {
        volatile unsigned* genp = (volatile unsigned*)&g_bar_gen;
        const unsigned g = *genp;
        __threadfence();
        if (atomicAdd(&g_bar_count, 1u) == expected - 1u) {
            g_bar_count = 0u;
            __threadfence();
            atomicAdd(&g_bar_gen, 1u);
        } else {
            while (*genp == g) __nanosleep(64);
            __threadfence();
        }
    }
    __syncthreads();
}

// Warp-level: dedup-gather-sum of src over one edge.
__device__ __forceinline__ void edge_reduce(const int* __restrict__ nidx, int e,
                                            const float2* __restrict__ src,
                                            int lane, unsigned lt,
                                            int& n, bool& keep, float& s0, float& s1) {
    n = nidx[e * DEG + lane];
    const unsigned peers = __match_any_sync(0xffffffffu, n);
    keep = (peers & lt) == 0u;
    s0 = 0.f; s1 = 0.f;
    if (keep) { const float2 pv = src[n]; s0 = pv.x; s1 = pv.y; }
    #pragma unroll
    for (int o = 16; o > 0; o >>= 1) {
        s0 += __shfl_xor_sync(0xffffffffu, s0, o);
        s1 += __shfl_xor_sync(0xffffffffu, s1, o);
    }
}

__global__ void __launch_bounds__(256, 4)
k_all(const float* __restrict__ x0,
      const float* __restrict__ Wl1, const float* __restrict__ Wl2,
      const float* __restrict__ Wm1, const float* __restrict__ bm1,
      const float* __restrict__ Wm2, const float* __restrict__ bm2,
      const float* __restrict__ Wm3, const float* __restrict__ bm3,
      const int* __restrict__ nidx, float* __restrict__ out, int CB) {
    const int t    = threadIdx.x;
    const int bid  = blockIdx.x;
    const int lane = t & 31;
    const unsigned ep1 = *(volatile unsigned*)&g_epoch + 1u;   // this launch's tag

    if (bid < CB) {
        // ---------- fold affine chain into M (32x2) + c (redundant per block) ----
        __shared__ float q[D], u[D], v[D], w2u[D], M0[D], M1[D];
        if (t < D) {
            float s = 0.f;
            #pragma unroll
            for (int j = 0; j < D; ++j) s += Wm2[t * D + j] * Wm3[j];
            q[t] = s;
        }
        __syncthreads();
        if (t < D) {
            float su = 0.f, sv = 0.f;
            #pragma unroll
            for (int j = 0; j < D; ++j) {
                su += Wm1[t * D + j] * q[j];
                sv += Wm1[(D + t) * D + j] * q[j];
            }
            u[t] = su; v[t] = sv;
        }
        __syncthreads();
        if (t < D) {
            float s = 0.f;
            #pragma unroll
            for (int j = 0; j < D; ++j) s += Wl2[t * D + j] * u[j];
            w2u[t] = s;
        }
        if (bid == 0 && t == 0) {
            float c = bm3[0];
            #pragma unroll
            for (int j = 0; j < D; ++j) c += bm1[j] * q[j] + bm2[j] * Wm3[j];
            g_c = c;
        }
        __syncthreads();
        if (t < D) {
            float s0 = 0.f, s1 = 0.f;
            #pragma unroll
            for (int j = 0; j < D; ++j) {
                s0 += Wl1[t * D + j] * w2u[j];
                s1 += Wl1[t * D + j] * v[j];
            }
            M0[t] = s0; M1[t] = s1;
        }
        __syncthreads();

        // ---------- p[n] = x0[n] @ M ; zero y, a -------------------------------
        for (int n = bid * 256 + t; n < NN; n += CB * 256) {
            const float4* row = (const float4*)(x0 + (size_t)n * D);
            float p0 = 0.f, p1 = 0.f;
            #pragma unroll
            for (int j = 0; j < 8; ++j) {
                const float4 xv = row[j];
                p0 += xv.x * M0[4*j] + xv.y * M0[4*j+1] + xv.z * M0[4*j+2] + xv.w * M0[4*j+3];
                p1 += xv.x * M1[4*j] + xv.y * M1[4*j+1] + xv.z * M1[4*j+2] + xv.w * M1[4*j+3];
            }
            g_p[n] = make_float2(p0, p1);
            g_y[n] = make_float2(0.f, 0.f);
            g_a[n] = 0.f;
        }
        chain_barrier((unsigned)CB);

        // ---------- zy: z[e] = Σ p[n∈e] ; y[n] += z[e] -------------------------
        const unsigned lt = (1u << lane) - 1u;
        const int CW = CB * 8;
        for (int e = bid * 8 + (t >> 5); e < NE; e += CW) {
            int n; bool keep; float s0, s1;
            edge_reduce(nidx, e, g_p, lane, lt, n, keep, s0, s1);
            if (keep) {
                atomicAdd(&g_y[n].x, s0);
                atomicAdd(&g_y[n].y, s1);
            }
        }
        chain_barrier((unsigned)CB);

        // ---------- ta: t[e] = Σ y[n∈e] ; b[e] = t.1 ; a[n] += t.0 -------------
        for (int e = bid * 8 + (t >> 5); e < NE; e += CW) {
            int n; bool keep; float s0, s1;
            edge_reduce(nidx, e, g_y, lane, lt, n, keep, s0, s1);
            if (lane == 0) g_b[e] = s1;
            if (keep) atomicAdd(&g_a[n], s0);
        }
        // publish a, b, c
        __threadfence();
        __syncthreads();
        if (t == 0) {
            if (atomicAdd(&g_chain_count, 1u) == (unsigned)CB - 1u) {
                g_chain_count = 0u;
                atomicExch(&g_chain_flag, ep1);
            }
        }
        // fall through: chain blocks join the fill
    }

    // ---------- zero-fill: per-block ticket queue, 1 row (32 KB) per grab ------
    {
        const float4 z4 = make_float4(0.f, 0.f, 0.f, 0.f);
        float4* out4 = (float4*)out;
        __shared__ unsigned s_t[2];
        if (t == 0) s_t[0] = atomicAdd(&g_ticket, 1u);
        __syncthreads();
        int par = 0;
        for (;;) {
            const unsigned cur = s_t[par];            // uniform row index
            if (cur >= (unsigned)NCHUNK) break;
            if (t == 0) s_t[par ^ 1] = atomicAdd(&g_ticket, 1u);
            float4* dst = out4 + (size_t)cur * CH4;
            #pragma unroll
            for (int j = 0; j < CH4 / 256; ++j)       // 8 x STG.128 per thread
                __stcs(&dst[t + j * 256], z4);
            __threadfence();                          // stores visible before flag
            __syncthreads();                          // all threads fenced; ticket ready
            if (t == 0) atomicExch(&g_cflag[cur], ep1);
            par ^= 1;
        }
    }

    // ---------- scatter: per-row dependency, no global barrier ------------------
    {
        // wait for a, b, c (chain finished long before tickets ran out in practice)
        if (t == 0) {
            volatile unsigned* cf = (volatile unsigned*)&g_chain_flag;
            while (*cf != ep1) __nanosleep(64);
        }
        __syncthreads();
        __threadfence();
        const float cc = g_c;
        for (int i = bid * 256 + t; i < NNZC; i += gridDim.x * 256) {
            const int n = __ldg(&nidx[i]);
            const int e = i >> 5;      // edge_idx = repeat(arange(E), DEG)
            volatile unsigned* rf = (volatile unsigned*)&g_cflag[n];
            while (*rf != ep1) __nanosleep(32);        // row zeros committed?
            __threadfence();
            out[(size_t)n * NE + e] = g_a[n] + g_b[e] + cc;
        }
    }

    // ---------- exit: last block resets queue state and bumps epoch -------------
    __syncthreads();
    if (t == 0) {
        __threadfence();
        if (atomicAdd(&g_exit, 1u) == gridDim.x - 1u) {
            g_exit   = 0u;
            g_ticket = 0u;           // safe: every block has left the fill loop
            atomicExch(&g_epoch, ep1);
        }
    }
}

extern "C" void kernel_launch(void* const* d_in, const int* in_sizes, int n_in,
                              void* d_out, int out_size) {
    const float* x0   = (const float*)d_in[0];
    // d_in[1] = dense incidence (unused)
    const float* Wl1  = (const float*)d_in[2];
    const float* Wl2  = (const float*)d_in[3];
    const float* Wm1  = (const float*)d_in[4];
    const float* bm1  = (const float*)d_in[5];
    const float* Wm2  = (const float*)d_in[6];
    const float* bm2  = (const float*)d_in[7];
    const float* Wm3  = (const float*)d_in[8];
    const float* bm3  = (const float*)d_in[9];
    const int*   nidx = (const int*)d_in[10];
    // d_in[11] = edge_idx (implied: e = i >> 5)

    int dev = 0;
    cudaGetDevice(&dev);
    int sms = 0;
    cudaDeviceGetAttribute(&sms, cudaDevAttrMultiProcessorCount, dev);
    int nb = 0;
    cudaOccupancyMaxActiveBlocksPerMultiprocessor(&nb, k_all, 256, 0);
    if (sms <= 0) sms = 148;
    if (nb  <= 0) nb  = 4;
    if (nb  >  4) nb  = 4;     // R4/R6-proven stream layout
    int grid = sms * nb;
    int cb = grid / 2 < 128 ? grid / 2 : 128;

    k_all<<<grid, 256>>>(x0, Wl1, Wl2, Wm1, bm1, Wm2, bm2, Wm3, bm3,
                         nidx, (float*)d_out, cb);
}